// round 1
// baseline (speedup 1.0000x reference)
#include <cuda_runtime.h>
#include <cuda_bf16.h>

#define B_ROWS 16384
#define L_COLS 1024

// Scratch for per-row losses (no device allocation allowed).
__device__ float g_row_loss[B_ROWS];

// One block per row; 256 threads; each thread loads one float4 of c and one
// int4 of y (256*4 = 1024 elements). Computes pos = sum y*exp(-c),
// neg = sum (1-y)*exp(c), yn = sum y, then loss = pos*neg/(yn*(L-yn)).
__global__ void __launch_bounds__(256, 8)
bpmll_row_kernel(const float* __restrict__ c, const int* __restrict__ y,
                 float* __restrict__ row_loss) {
    const int row = blockIdx.x;
    const int t = threadIdx.x;

    const float4 cv = reinterpret_cast<const float4*>(
        c + (size_t)row * L_COLS)[t];
    const int4 yv = reinterpret_cast<const int4*>(
        y + (size_t)row * L_COLS)[t];

    float pos = 0.0f, neg = 0.0f;
    int yc = 0;

    {
        float e = __expf(cv.x);
        if (yv.x) { pos += 1.0f / e; yc++; } else { neg += e; }
    }
    {
        float e = __expf(cv.y);
        if (yv.y) { pos += 1.0f / e; yc++; } else { neg += e; }
    }
    {
        float e = __expf(cv.z);
        if (yv.z) { pos += 1.0f / e; yc++; } else { neg += e; }
    }
    {
        float e = __expf(cv.w);
        if (yv.w) { pos += 1.0f / e; yc++; } else { neg += e; }
    }

    // Warp tree reduction (deterministic).
    #pragma unroll
    for (int off = 16; off > 0; off >>= 1) {
        pos += __shfl_down_sync(0xFFFFFFFFu, pos, off);
        neg += __shfl_down_sync(0xFFFFFFFFu, neg, off);
        yc  += __shfl_down_sync(0xFFFFFFFFu, yc, off);
    }

    __shared__ float s_pos[8], s_neg[8];
    __shared__ int s_yc[8];
    const int warp = t >> 5;
    const int lane = t & 31;
    if (lane == 0) { s_pos[warp] = pos; s_neg[warp] = neg; s_yc[warp] = yc; }
    __syncthreads();

    if (t == 0) {
        float P = 0.0f, N = 0.0f;
        int Y = 0;
        #pragma unroll
        for (int w = 0; w < 8; w++) { P += s_pos[w]; N += s_neg[w]; Y += s_yc[w]; }
        const float yn = (float)Y;
        const float ybn = (float)(L_COLS - Y);
        row_loss[row] = (P * N) / (yn * ybn);
    }
}

// Single-block deterministic reduction of 16384 row losses -> mean.
__global__ void __launch_bounds__(512)
bpmll_reduce_kernel(const float* __restrict__ row_loss, float* __restrict__ out) {
    const int t = threadIdx.x;
    float s = 0.0f;
    // 16384 / 512 = 32 values per thread, fixed order.
    #pragma unroll 8
    for (int i = t; i < B_ROWS; i += 512) s += row_loss[i];

    #pragma unroll
    for (int off = 16; off > 0; off >>= 1)
        s += __shfl_down_sync(0xFFFFFFFFu, s, off);

    __shared__ float s_w[16];
    const int warp = t >> 5;
    const int lane = t & 31;
    if (lane == 0) s_w[warp] = s;
    __syncthreads();

    if (t == 0) {
        float tot = 0.0f;
        #pragma unroll
        for (int w = 0; w < 16; w++) tot += s_w[w];
        out[0] = tot * (1.0f / (float)B_ROWS);
    }
}

extern "C" void kernel_launch(void* const* d_in, const int* in_sizes, int n_in,
                              void* d_out, int out_size) {
    const float* c = (const float*)d_in[0];
    const int* y = (const int*)d_in[1];
    float* out = (float*)d_out;

    float* row_loss = nullptr;
    cudaGetSymbolAddress((void**)&row_loss, g_row_loss);

    bpmll_row_kernel<<<B_ROWS, 256>>>(c, y, row_loss);
    bpmll_reduce_kernel<<<1, 512>>>(row_loss, out);
}

// round 2
// speedup vs baseline: 1.2257x; 1.2257x over previous
#include <cuda_runtime.h>
#include <cuda_bf16.h>

#define B_ROWS 16384
#define L_COLS 1024
#define ROWS_PER_BLK 8
#define NBLKS (B_ROWS / ROWS_PER_BLK)   // 2048

// Per-block partial sums of row losses (no device allocation allowed).
__device__ float g_partials[NBLKS];

// 2048 blocks x 256 threads. Warp w handles row blockIdx.x*8 + w.
// Each lane does 8 iterations of (float4 c, int4 y) -> 1024 elems/row.
// Only one __expf per element: e = exp(y ? -c : c).
__global__ void __launch_bounds__(256)
bpmll_row_kernel(const float* __restrict__ c, const int* __restrict__ y,
                 float* __restrict__ partials) {
    const int t = threadIdx.x;
    const int warp = t >> 5;
    const int lane = t & 31;
    const int row = blockIdx.x * ROWS_PER_BLK + warp;

    const float4* __restrict__ c4 =
        reinterpret_cast<const float4*>(c + (size_t)row * L_COLS);
    const int4* __restrict__ y4 =
        reinterpret_cast<const int4*>(y + (size_t)row * L_COLS);

    float pos = 0.0f, neg = 0.0f;
    int yc = 0;

    #pragma unroll
    for (int i = 0; i < 8; i++) {
        const float4 cv = c4[i * 32 + lane];
        const int4 yv = y4[i * 32 + lane];

        {
            const float e = __expf(yv.x ? -cv.x : cv.x);
            if (yv.x) { pos += e; yc++; } else { neg += e; }
        }
        {
            const float e = __expf(yv.y ? -cv.y : cv.y);
            if (yv.y) { pos += e; yc++; } else { neg += e; }
        }
        {
            const float e = __expf(yv.z ? -cv.z : cv.z);
            if (yv.z) { pos += e; yc++; } else { neg += e; }
        }
        {
            const float e = __expf(yv.w ? -cv.w : cv.w);
            if (yv.w) { pos += e; yc++; } else { neg += e; }
        }
    }

    // Warp tree reduction (deterministic).
    #pragma unroll
    for (int off = 16; off > 0; off >>= 1) {
        pos += __shfl_down_sync(0xFFFFFFFFu, pos, off);
        neg += __shfl_down_sync(0xFFFFFFFFu, neg, off);
        yc  += __shfl_down_sync(0xFFFFFFFFu, yc, off);
    }

    __shared__ float s_loss[ROWS_PER_BLK];
    if (lane == 0) {
        const float yn = (float)yc;
        const float ybn = (float)(L_COLS - yc);
        s_loss[warp] = (pos * neg) / (yn * ybn);
    }
    __syncthreads();

    if (t == 0) {
        float sum = 0.0f;
        #pragma unroll
        for (int w = 0; w < ROWS_PER_BLK; w++) sum += s_loss[w];
        partials[blockIdx.x] = sum;
    }
}

// Single-block reduction of 2048 partials -> mean over 16384 rows.
__global__ void __launch_bounds__(512)
bpmll_reduce_kernel(const float* __restrict__ partials, float* __restrict__ out) {
    const int t = threadIdx.x;
    const float4 v = reinterpret_cast<const float4*>(partials)[t];  // 512*4 = 2048
    float s = v.x + v.y + v.z + v.w;

    #pragma unroll
    for (int off = 16; off > 0; off >>= 1)
        s += __shfl_down_sync(0xFFFFFFFFu, s, off);

    __shared__ float s_w[16];
    const int warp = t >> 5;
    const int lane = t & 31;
    if (lane == 0) s_w[warp] = s;
    __syncthreads();

    if (t == 0) {
        float tot = 0.0f;
        #pragma unroll
        for (int w = 0; w < 16; w++) tot += s_w[w];
        out[0] = tot * (1.0f / (float)B_ROWS);
    }
}

extern "C" void kernel_launch(void* const* d_in, const int* in_sizes, int n_in,
                              void* d_out, int out_size) {
    const float* c = (const float*)d_in[0];
    const int* y = (const int*)d_in[1];
    float* out = (float*)d_out;

    float* partials = nullptr;
    cudaGetSymbolAddress((void**)&partials, g_partials);

    bpmll_row_kernel<<<NBLKS, 256>>>(c, y, partials);
    bpmll_reduce_kernel<<<1, 512>>>(partials, out);
}